// round 13
// baseline (speedup 1.0000x reference)
#include <cuda_runtime.h>
#include <cuda_fp16.h>
#include <cstdint>

#define Bdim 2
#define Tdim 2048
#define Edim 1024
#define Hdim 16
#define HD 64
#define QKV3 192

// Attention tiling
#define NW 2               // warps per block
#define MBLK 64            // queries per block (32 per warp)
#define NTILE 64           // keys per iteration
#define NIT (Tdim / NTILE) // 32
#define HSTR 72            // smem row stride in fp16 elems (144 B)
#define HSTRU 36           // ... in u32 units

// QKV GEMM tiling
#define QTHREADS 128
#define MROWS 128          // (b,t) rows per block
#define XSTR 72            // x smem stride (halfs)
#define WSTR 200           // W smem stride (halfs)

#define LOG2E 1.4426950408889634f
#define QSCALE (0.125f * LOG2E)
#define ONES2 0x3C003C00u  // f16x2 {1.0, 1.0}

// Scratch: Q/K/V in [B, H, T, HD] layout, fp16.
// Q pre-scaled by 0.125*log2(e) (softmax in exp2 domain).
__device__ __half g_Q[Bdim * Hdim * Tdim * HD];
__device__ __half g_K[Bdim * Hdim * Tdim * HD];
__device__ __half g_V[Bdim * Hdim * Tdim * HD];

// ---------------------------------------------------------------------------
// helpers
// ---------------------------------------------------------------------------
__device__ __forceinline__ float ex2(float x) {
    float y;
    asm("ex2.approx.ftz.f32 %0, %1;" : "=f"(y) : "f"(x));
    return y;
}
// d = {lo in lower half, hi in upper half} packed f16x2
__device__ __forceinline__ uint32_t f16x2(float hi, float lo) {
    uint32_t d;
    asm("cvt.rn.f16x2.f32 %0, %1, %2;" : "=r"(d) : "f"(hi), "f"(lo));
    return d;
}
// packed fp16 exp2 of both halves
__device__ __forceinline__ uint32_t h2ex2(uint32_t a) {
    uint32_t d;
    asm("ex2.approx.f16x2 %0, %1;" : "=r"(d) : "r"(a));
    return d;
}
__device__ __forceinline__ void mma_f16(
    float& c0, float& c1, float& c2, float& c3,
    uint32_t a0, uint32_t a1, uint32_t a2, uint32_t a3,
    uint32_t b0, uint32_t b1)
{
    asm volatile(
        "mma.sync.aligned.m16n8k16.row.col.f32.f16.f16.f32 "
        "{%0,%1,%2,%3}, {%4,%5,%6,%7}, {%8,%9}, {%0,%1,%2,%3};"
        : "+f"(c0), "+f"(c1), "+f"(c2), "+f"(c3)
        : "r"(a0), "r"(a1), "r"(a2), "r"(a3), "r"(b0), "r"(b1));
}
__device__ __forceinline__ void ldsm_x4(
    uint32_t& r0, uint32_t& r1, uint32_t& r2, uint32_t& r3, uint32_t saddr)
{
    asm volatile(
        "ldmatrix.sync.aligned.m8n8.x4.shared.b16 {%0,%1,%2,%3}, [%4];"
        : "=r"(r0), "=r"(r1), "=r"(r2), "=r"(r3) : "r"(saddr));
}
__device__ __forceinline__ void ldsm_x4_trans(
    uint32_t& r0, uint32_t& r1, uint32_t& r2, uint32_t& r3, uint32_t saddr)
{
    asm volatile(
        "ldmatrix.sync.aligned.m8n8.x4.trans.shared.b16 {%0,%1,%2,%3}, [%4];"
        : "=r"(r0), "=r"(r1), "=r"(r2), "=r"(r3) : "r"(saddr));
}
__device__ __forceinline__ void cp_async16(uint32_t smem_dst, const void* gmem_src) {
    asm volatile("cp.async.cg.shared.global [%0], [%1], 16;"
                 :: "r"(smem_dst), "l"(gmem_src) : "memory");
}
__device__ __forceinline__ void cp_commit() {
    asm volatile("cp.async.commit_group;" ::: "memory");
}
__device__ __forceinline__ void cp_wait1() {
    asm volatile("cp.async.wait_group 1;" ::: "memory");
}

// ---------------------------------------------------------------------------
// Kernel 1: QKV projection as an fp16 tensor-core GEMM. (verified R12)
// ---------------------------------------------------------------------------
__global__ __launch_bounds__(QTHREADS) void qkv_mma_kernel(
    const float* __restrict__ x,      // [B, T, E]
    const float* __restrict__ W,      // [64, 192]
    const float* __restrict__ bias)   // [192]
{
    __shared__ __align__(16) __half xA[MROWS * XSTR];
    __shared__ __align__(16) __half Wk[64 * WSTR];

    const int tid  = threadIdx.x;
    const int w    = tid >> 5;
    const int lane = tid & 31;
    const int gid  = lane >> 2;
    const int tig  = lane & 3;

    const int bt0 = blockIdx.x * MROWS;
    const int h   = blockIdx.y;
    const int b   = bt0 >> 11;
    const int t0  = bt0 & 2047;

#pragma unroll
    for (int i = 0; i < 16; i++) {
        int idx = tid + QTHREADS * i;
        int r = idx >> 4, c4 = (idx & 15) * 4;
        float4 v = *(const float4*)(x + (size_t)(bt0 + r) * Edim + h * HD + c4);
        __half2* dst = (__half2*)(xA + r * XSTR + c4);
        dst[0] = __floats2half2_rn(v.x, v.y);
        dst[1] = __floats2half2_rn(v.z, v.w);
    }
#pragma unroll
    for (int i = 0; i < 24; i++) {
        int idx = tid + QTHREADS * i;
        int k = idx / 48, c4 = (idx % 48) * 4;
        float4 v = *(const float4*)(W + k * QKV3 + c4);
        __half2* dst = (__half2*)(Wk + k * WSTR + c4);
        dst[0] = __floats2half2_rn(v.x, v.y);
        dst[1] = __floats2half2_rn(v.z, v.w);
    }
    __syncthreads();

    const uint32_t xA_base = (uint32_t)__cvta_generic_to_shared(xA);
    const uint32_t Wk_base = (uint32_t)__cvta_generic_to_shared(Wk);

    const int lr = ((lane >> 3) & 1) * 8 + (lane & 7);
    const int lc = (lane >> 4) * 8;

    uint32_t bf[4][6][2];
#pragma unroll
    for (int kt = 0; kt < 4; kt++)
#pragma unroll
        for (int nb = 0; nb < 3; nb++) {
            uint32_t saddr = Wk_base + (kt * 16 + lr) * (WSTR * 2)
                           + (w * 48 + nb * 16 + lc) * 2;
            ldsm_x4_trans(bf[kt][2 * nb][0], bf[kt][2 * nb][1],
                          bf[kt][2 * nb + 1][0], bf[kt][2 * nb + 1][1], saddr);
        }

    float bx[6], by[6], scl[6];
    __half* dbase[6];
#pragma unroll
    for (int nt = 0; nt < 6; nt++) {
        int n = w * 48 + nt * 8 + 2 * tig;
        bx[nt] = bias[n];
        by[nt] = bias[n + 1];
        int g = 6 * w + nt;
        int part = g >> 3;
        scl[nt] = (part == 0) ? QSCALE : 1.f;
        __half* base = (part == 0) ? g_Q : (part == 1) ? g_K : g_V;
        dbase[nt] = base + ((size_t)(b * Hdim + h) * Tdim) * HD
                  + (g & 7) * 8 + 2 * tig;
    }

#pragma unroll
    for (int mt = 0; mt < 8; mt++) {
        uint32_t af[4][4];
#pragma unroll
        for (int kt = 0; kt < 4; kt++) {
            uint32_t saddr = xA_base + (mt * 16 + (lane & 15)) * (XSTR * 2)
                           + kt * 32 + (lane >> 4) * 16;
            ldsm_x4(af[kt][0], af[kt][1], af[kt][2], af[kt][3], saddr);
        }
        const int t = t0 + mt * 16 + gid;
#pragma unroll
        for (int nt = 0; nt < 6; nt++) {
            float c0 = 0.f, c1 = 0.f, c2 = 0.f, c3 = 0.f;
#pragma unroll
            for (int kt = 0; kt < 4; kt++)
                mma_f16(c0, c1, c2, c3,
                        af[kt][0], af[kt][1], af[kt][2], af[kt][3],
                        bf[kt][nt][0], bf[kt][nt][1]);
            c0 = (c0 + bx[nt]) * scl[nt];
            c1 = (c1 + by[nt]) * scl[nt];
            c2 = (c2 + bx[nt]) * scl[nt];
            c3 = (c3 + by[nt]) * scl[nt];
            *(__half2*)(dbase[nt] + (size_t)t * HD)       = __floats2half2_rn(c0, c1);
            *(__half2*)(dbase[nt] + (size_t)(t + 8) * HD) = __floats2half2_rn(c2, c3);
        }
    }
}

// ---------------------------------------------------------------------------
// Kernel 2: fp16 tensor-core flash attention, m32 per warp, register P.
// fp16x2 exp -> PV A-frags directly; l via ones-B MMA; lazy o-rescale.
// ---------------------------------------------------------------------------
#define TILE_H (NTILE * HSTR)                // fp16 elems per tile = 4608
#define SMEM_BYTES (2 * 2 * TILE_H * 2)      // K+V, 2 stages: 36864 B

__global__ __launch_bounds__(32 * NW) void attn_kernel(float* __restrict__ out)
{
    extern __shared__ __align__(16) __half sm[];
    __half* smK = sm;               // [2][NTILE][HSTR]
    __half* smV = sm + 2 * TILE_H;  // [2][NTILE][HSTR]

    const int tid  = threadIdx.x;
    const int w    = tid >> 5;
    const int lane = tid & 31;
    const int gid  = lane >> 2;
    const int tig  = lane & 3;

    const int bh = blockIdx.y;
    const int b  = bh >> 4;
    const int h  = bh & 15;

    const __half* Kg = g_K + (size_t)bh * Tdim * HD;
    const __half* Vg = g_V + (size_t)bh * Tdim * HD;

    const uint32_t smK_base = (uint32_t)__cvta_generic_to_shared(smK);
    const uint32_t smV_base = (uint32_t)__cvta_generic_to_shared(smV);

    int cprow[8], cpcol[8];
#pragma unroll
    for (int i = 0; i < 8; i++) {
        int v = tid + 64 * i;
        cprow[i] = v >> 3;
        cpcol[i] = v & 7;
    }

    // ---- issue tile 0 ----
#pragma unroll
    for (int i = 0; i < 8; i++) {
        cp_async16(smK_base + cprow[i] * 144 + cpcol[i] * 16,
                   Kg + cprow[i] * HD + cpcol[i] * 8);
        cp_async16(smV_base + cprow[i] * 144 + cpcol[i] * 16,
                   Vg + cprow[i] * HD + cpcol[i] * 8);
    }
    cp_commit();

    // ---- Q fragments: two m16 tiles ----
    const int qrow0 = blockIdx.x * MBLK + w * 32 + gid;
    uint32_t qf[2][4][4];
#pragma unroll
    for (int mt = 0; mt < 2; mt++) {
        const uint32_t* Qm =
            (const uint32_t*)(g_Q + ((size_t)bh * Tdim + qrow0 + mt * 16) * HD);
        const uint32_t* Qm8 = Qm + 8 * (HD / 2);
#pragma unroll
        for (int kt = 0; kt < 4; kt++) {
            qf[mt][kt][0] = Qm[8 * kt + tig];
            qf[mt][kt][1] = Qm8[8 * kt + tig];
            qf[mt][kt][2] = Qm[8 * kt + tig + 4];
            qf[mt][kt][3] = Qm8[8 * kt + tig + 4];
        }
    }

    float o[2][8][4];
#pragma unroll
    for (int mt = 0; mt < 2; mt++)
#pragma unroll
        for (int nt = 0; nt < 8; nt++)
#pragma unroll
            for (int i = 0; i < 4; i++) o[mt][nt][i] = 0.f;

    float mrow[2][2], lrow[2][2];
#pragma unroll
    for (int mt = 0; mt < 2; mt++) {
        mrow[mt][0] = -1e30f; mrow[mt][1] = -1e30f;
        lrow[mt][0] = 0.f;    lrow[mt][1] = 0.f;
    }

    const int lr = ((lane >> 3) & 1) * 8 + (lane & 7);
    const int lc = (lane >> 4) * 8;

    for (int it = 0; it < NIT; it++) {
        const int st = it & 1;
        const uint32_t stV = smV_base + st * TILE_H * 2;

        if (it + 1 < NIT) {
            const int ns = (it + 1) & 1;
            const __half* Kn = Kg + (size_t)(it + 1) * NTILE * HD;
            const __half* Vn = Vg + (size_t)(it + 1) * NTILE * HD;
            const uint32_t dK = smK_base + ns * TILE_H * 2;
            const uint32_t dV = smV_base + ns * TILE_H * 2;
#pragma unroll
            for (int i = 0; i < 8; i++) {
                cp_async16(dK + cprow[i] * 144 + cpcol[i] * 16,
                           Kn + cprow[i] * HD + cpcol[i] * 8);
                cp_async16(dV + cprow[i] * 144 + cpcol[i] * 16,
                           Vn + cprow[i] * HD + cpcol[i] * 8);
            }
        }
        cp_commit();
        cp_wait1();
        __syncthreads();

        const uint32_t* Kt = (const uint32_t*)(smK + st * TILE_H);

        // ---- S = Q K^T : 8 key n-tiles x 4 k16-tiles, shared B-frags ----
        float sc[2][8][4];
#pragma unroll
        for (int nt = 0; nt < 8; nt++) {
#pragma unroll
            for (int mt = 0; mt < 2; mt++)
#pragma unroll
                for (int i = 0; i < 4; i++) sc[mt][nt][i] = 0.f;
            const uint32_t* kr = Kt + (nt * 8 + gid) * HSTRU;
#pragma unroll
            for (int kt = 0; kt < 4; kt++) {
                uint32_t b0 = kr[8 * kt + tig];
                uint32_t b1 = kr[8 * kt + tig + 4];
                mma_f16(sc[0][nt][0], sc[0][nt][1], sc[0][nt][2], sc[0][nt][3],
                        qf[0][kt][0], qf[0][kt][1], qf[0][kt][2], qf[0][kt][3],
                        b0, b1);
                mma_f16(sc[1][nt][0], sc[1][nt][1], sc[1][nt][2], sc[1][nt][3],
                        qf[1][kt][0], qf[1][kt][1], qf[1][kt][2], qf[1][kt][3],
                        b0, b1);
            }
        }

        // ---- online softmax: f16x2 exp directly into PV A-frags;
        //      l via ones-B MMA; lazy o-rescale. ----
        uint32_t pa[2][4][4];
#pragma unroll
        for (int mt = 0; mt < 2; mt++) {
            float rm0 = -1e30f, rm1 = -1e30f;
#pragma unroll
            for (int nt = 0; nt < 8; nt++) {
                rm0 = fmaxf(rm0, fmaxf(sc[mt][nt][0], sc[mt][nt][1]));
                rm1 = fmaxf(rm1, fmaxf(sc[mt][nt][2], sc[mt][nt][3]));
            }
            rm0 = fmaxf(rm0, __shfl_xor_sync(0xffffffffu, rm0, 1));
            rm0 = fmaxf(rm0, __shfl_xor_sync(0xffffffffu, rm0, 2));
            rm1 = fmaxf(rm1, __shfl_xor_sync(0xffffffffu, rm1, 1));
            rm1 = fmaxf(rm1, __shfl_xor_sync(0xffffffffu, rm1, 2));

            const float nm0 = fmaxf(mrow[mt][0], rm0);
            const float nm1 = fmaxf(mrow[mt][1], rm1);
            const float corr0 = ex2(mrow[mt][0] - nm0);
            const float corr1 = ex2(mrow[mt][1] - nm1);
            mrow[mt][0] = nm0; mrow[mt][1] = nm1;

            // exp2 in packed fp16: output IS the PV A-fragment
#pragma unroll
            for (int kt2 = 0; kt2 < 4; kt2++) {
                pa[mt][kt2][0] = h2ex2(f16x2(sc[mt][2 * kt2][1] - nm0,
                                             sc[mt][2 * kt2][0] - nm0));
                pa[mt][kt2][1] = h2ex2(f16x2(sc[mt][2 * kt2][3] - nm1,
                                             sc[mt][2 * kt2][2] - nm1));
                pa[mt][kt2][2] = h2ex2(f16x2(sc[mt][2 * kt2 + 1][1] - nm0,
                                             sc[mt][2 * kt2 + 1][0] - nm0));
                pa[mt][kt2][3] = h2ex2(f16x2(sc[mt][2 * kt2 + 1][3] - nm1,
                                             sc[mt][2 * kt2 + 1][2] - nm1));
            }

            // l row-sum = P @ ones via MMA (constant all-ones B fragment).
            // Every lane of a row quad gets the full row sum in c0/c2.
            float c0 = 0.f, c1 = 0.f, c2 = 0.f, c3 = 0.f;
#pragma unroll
            for (int kt2 = 0; kt2 < 4; kt2++)
                mma_f16(c0, c1, c2, c3,
                        pa[mt][kt2][0], pa[mt][kt2][1],
                        pa[mt][kt2][2], pa[mt][kt2][3],
                        ONES2, ONES2);
            lrow[mt][0] = lrow[mt][0] * corr0 + c0;
            lrow[mt][1] = lrow[mt][1] * corr1 + c2;

            // Rescale o only when some row's max actually moved.
            if (!__all_sync(0xffffffffu, (corr0 == 1.f) && (corr1 == 1.f))) {
#pragma unroll
                for (int nt = 0; nt < 8; nt++) {
                    o[mt][nt][0] *= corr0; o[mt][nt][1] *= corr0;
                    o[mt][nt][2] *= corr1; o[mt][nt][3] *= corr1;
                }
            }
        }

        // ---- O += P V : B-frags via ldmatrix.x4.trans ----
#pragma unroll
        for (int kt2 = 0; kt2 < 4; kt2++) {
#pragma unroll
            for (int nh = 0; nh < 4; nh++) {
                uint32_t saddr = stV + (kt2 * 16 + lr) * 144 + (nh * 16 + lc) * 2;
                uint32_t v0, v1, v2, v3;
                ldsm_x4_trans(v0, v1, v2, v3, saddr);
                mma_f16(o[0][2 * nh][0], o[0][2 * nh][1],
                        o[0][2 * nh][2], o[0][2 * nh][3],
                        pa[0][kt2][0], pa[0][kt2][1], pa[0][kt2][2], pa[0][kt2][3],
                        v0, v1);
                mma_f16(o[1][2 * nh][0], o[1][2 * nh][1],
                        o[1][2 * nh][2], o[1][2 * nh][3],
                        pa[1][kt2][0], pa[1][kt2][1], pa[1][kt2][2], pa[1][kt2][3],
                        v0, v1);
                mma_f16(o[0][2 * nh + 1][0], o[0][2 * nh + 1][1],
                        o[0][2 * nh + 1][2], o[0][2 * nh + 1][3],
                        pa[0][kt2][0], pa[0][kt2][1], pa[0][kt2][2], pa[0][kt2][3],
                        v2, v3);
                mma_f16(o[1][2 * nh + 1][0], o[1][2 * nh + 1][1],
                        o[1][2 * nh + 1][2], o[1][2 * nh + 1][3],
                        pa[1][kt2][0], pa[1][kt2][1], pa[1][kt2][2], pa[1][kt2][3],
                        v2, v3);
            }
        }

        __syncthreads();
    }

    // ---- epilogue: l already a full row-sum (uniform across the quad) ----
#pragma unroll
    for (int mt = 0; mt < 2; mt++) {
        const float inv0 = 1.f / lrow[mt][0];
        const float inv1 = 1.f / lrow[mt][1];

        float* orow0 = out + ((size_t)(b * Tdim + qrow0 + mt * 16)) * Edim + h * HD;
        float* orow1 = orow0 + 8 * (size_t)Edim;
#pragma unroll
        for (int nt = 0; nt < 8; nt++) {
            float2* d0 = (float2*)&orow0[nt * 8 + 2 * tig];
            float2* d1 = (float2*)&orow1[nt * 8 + 2 * tig];
            *d0 = make_float2(o[mt][nt][0] * inv0, o[mt][nt][1] * inv0);
            *d1 = make_float2(o[mt][nt][2] * inv1, o[mt][nt][3] * inv1);
        }
    }
}

// ---------------------------------------------------------------------------
extern "C" void kernel_launch(void* const* d_in, const int* in_sizes, int n_in,
                              void* d_out, int out_size)
{
    const float* x    = (const float*)d_in[0];   // [2, 2048, 1024]
    const float* W    = (const float*)d_in[1];   // [64, 192]
    const float* bias = (const float*)d_in[2];   // [192]
    float* out = (float*)d_out;                  // [2, 2048, 1024]

    dim3 qgrid(Bdim * Tdim / MROWS, Hdim);       // 32 x 16 = 512 blocks
    qkv_mma_kernel<<<qgrid, QTHREADS>>>(x, W, bias);

    cudaFuncSetAttribute(attn_kernel,
                         cudaFuncAttributeMaxDynamicSharedMemorySize,
                         SMEM_BYTES);
    dim3 grid(Tdim / MBLK, Bdim * Hdim);         // 32 x 32 = 1024 blocks
    attn_kernel<<<grid, 32 * NW, SMEM_BYTES>>>(out);
}